// round 1
// baseline (speedup 1.0000x reference)
#include <cuda_runtime.h>
#include <cuda_bf16.h>
#include <math.h>
#include <stdint.h>

// Problem constants
#define Bn  32
#define Cc  80
#define TXn 512
#define TYn 2048
#define K2  160          // stacked K: [scale(80); mean*scale(80)]
#define NEGV (-1e9f)
#define LOG2PI 1.8378770664093453f

// Output layout (flat f32, reference return order)
#define Z_OFF        0
#define YMEAN_OFF    (Bn*Cc*TYn)               // 5242880
#define YLOG_OFF     (2*Bn*Cc*TYn)             // 10485760
#define ATTN_OFF     (3*Bn*Cc*TYn)             // 15728640
#define ODUR_OFF     (ATTN_OFF + Bn*TYn*TXn)   // 49283072
#define OADUR_OFF    (ODUR_OFF + Bn*TXn)       // 49299456

// -------------------- scratch (__device__ globals, zero-initialized) ------
__device__ float    g_W[Bn*K2*TXn];            // 10.5 MB  [b][k][x]
__device__ float    g_Z[Bn*K2*TYn];            // 42 MB    [b][k][y]
__device__ float    g_rowA[Bn*TXn];            // logp1+logp4 per (b,x)
__device__ float    g_logpT[(size_t)Bn*TYn*TXn]; // 134 MB [b][y][x]
__device__ unsigned g_dbits[(size_t)Bn*TYn*32];  // 8 MB dir bits, 16/lane-word
__device__ int      g_xy[Bn*TYn];              // alignment index per (b,y)
__device__ int      g_cnt[Bn*TXn];             // per-x duration counts

// -------------------- K1: per-(b,x) prep -----------------------------------
__global__ void prepx_kernel(const float* __restrict__ om,
                             const float* __restrict__ ols,
                             const float* __restrict__ odur,
                             float* __restrict__ out)
{
    int i = blockIdx.x * blockDim.x + threadIdx.x;
    if (i >= Bn*TXn) return;
    int b = i / TXn, x = i % TXn;
    const float* omb = om  + (size_t)b*Cc*TXn + x;
    const float* olb = ols + (size_t)b*Cc*TXn + x;
    float* wS = g_W + (size_t)b*K2*TXn + x;
    float sa = 0.f;
    #pragma unroll 4
    for (int c = 0; c < Cc; c++) {
        float l  = olb[(size_t)c*TXn];
        float sc = expf(-2.f*l);
        float m  = omb[(size_t)c*TXn];
        wS[(size_t)c*TXn]        = sc;
        wS[(size_t)(Cc+c)*TXn]   = m*sc;
        sa += -0.5f*LOG2PI - l - 0.5f*m*m*sc;
    }
    g_rowA[i] = sa;
    g_cnt[i]  = 0;                      // zero histogram each launch
    out[ODUR_OFF + i] = odur[i];        // pass-through output
}

// -------------------- K2: z masking + Z matrix ------------------------------
__global__ void prepz_kernel(const float* __restrict__ z,
                             const int* __restrict__ yl,
                             float* __restrict__ out)
{
    int i = blockIdx.x * blockDim.x + threadIdx.x;
    if (i >= Bn*Cc*TYn) return;
    int b = i / (Cc*TYn);
    int r = i % (Cc*TYn);
    int c = r / TYn;
    int y = r % TYn;
    float zv = z[i];
    if (y >= yl[b]) zv = 0.f;
    out[Z_OFF + i] = zv;
    size_t zb = (size_t)b*K2*TYn;
    g_Z[zb + (size_t)c*TYn + y]      = -0.5f*zv*zv;
    g_Z[zb + (size_t)(Cc+c)*TYn + y] = zv;
}

// -------------------- K3: logp GEMM (64x64 tile, 256 thr, 4x4/thr) ----------
__global__ void __launch_bounds__(256)
gemm_kernel(const int* __restrict__ xl, const int* __restrict__ yl)
{
    int b  = blockIdx.z;
    int x0 = blockIdx.x * 64;
    int y0 = blockIdx.y * 64;
    int xlen = xl[b], ylen = yl[b];
    if (x0 >= xlen || y0 >= ylen) return;   // never read downstream

    __shared__ float zs[16][64];
    __shared__ float ws[16][64];

    int tid = threadIdx.x;
    int lr  = tid >> 4;          // 0..15 (smem load row)
    int lc4 = (tid & 15) << 2;   // 0..60
    int ty  = tid >> 4;          // 0..15
    int tx  = tid & 15;          // 0..15

    float acc[4][4] = {};
    const float* Zb = g_Z + (size_t)b*K2*TYn;
    const float* Wb = g_W + (size_t)b*K2*TXn;

    for (int k0 = 0; k0 < K2; k0 += 16) {
        *(float4*)&zs[lr][lc4] = *(const float4*)&Zb[(size_t)(k0+lr)*TYn + y0 + lc4];
        *(float4*)&ws[lr][lc4] = *(const float4*)&Wb[(size_t)(k0+lr)*TXn + x0 + lc4];
        __syncthreads();
        #pragma unroll
        for (int k = 0; k < 16; k++) {
            float4 zf = *(float4*)&zs[k][ty<<2];
            float4 wf = *(float4*)&ws[k][tx<<2];
            float za[4] = {zf.x, zf.y, zf.z, zf.w};
            float wa[4] = {wf.x, wf.y, wf.z, wf.w};
            #pragma unroll
            for (int i = 0; i < 4; i++)
                #pragma unroll
                for (int j = 0; j < 4; j++)
                    acc[i][j] += za[i]*wa[j];
        }
        __syncthreads();
    }

    float ra[4];
    #pragma unroll
    for (int j = 0; j < 4; j++)
        ra[j] = g_rowA[b*TXn + x0 + (tx<<2) + j];

    #pragma unroll
    for (int i = 0; i < 4; i++) {
        int y = y0 + (ty<<2) + i;
        float4 o;
        float* op = (float*)&o;
        #pragma unroll
        for (int j = 0; j < 4; j++) {
            int x = x0 + (tx<<2) + j;
            op[j] = (x < xlen && y < ylen) ? (acc[i][j] + ra[j]) : 0.f;
        }
        *(float4*)&g_logpT[((size_t)b*TYn + y)*TXn + x0 + (tx<<2)] = o;
    }
}

// -------------------- K4: forward Viterbi (1 warp per batch) ----------------
__global__ void __launch_bounds__(32)
fwd_kernel(const int* __restrict__ xl, const int* __restrict__ yl)
{
    int b = blockIdx.x, lane = threadIdx.x;
    int xlen = xl[b], ylen = yl[b];
    int xb = lane * 16;

    unsigned fbits;
    if (xb >= xlen)            fbits = 0xFFFFu;
    else if (xb + 16 <= xlen)  fbits = 0u;
    else                       fbits = (0xFFFFu << (xlen - xb)) & 0xFFFFu;

    float v[16];
    #pragma unroll
    for (int i = 0; i < 16; i++) v[i] = 0.f;

    const float4* colbase = (const float4*)(g_logpT + (size_t)b*TYn*TXn + xb);
    const int stride4 = TXn / 4;   // float4 stride between columns

    const int D = 4;
    float4 cb[D][4];
    #pragma unroll
    for (int d = 0; d < D; d++) {
        if (d < ylen) {
            const float4* p = colbase + (size_t)d * stride4;
            cb[d][0]=p[0]; cb[d][1]=p[1]; cb[d][2]=p[2]; cb[d][3]=p[3];
        }
    }

    for (int j0 = 0; j0 < ylen; j0 += D) {
        #pragma unroll
        for (int d = 0; d < D; d++) {
            int j = j0 + d;
            if (j < ylen) {
                float c[16];
                ((float4*)c)[0]=cb[d][0]; ((float4*)c)[1]=cb[d][1];
                ((float4*)c)[2]=cb[d][2]; ((float4*)c)[3]=cb[d][3];

                float left = __shfl_up_sync(0xFFFFFFFFu, v[15], 1);
                if (lane == 0) left = NEGV;

                unsigned w = 0;
                float pv = left;
                #pragma unroll
                for (int i = 0; i < 16; i++) {
                    float old = v[i];
                    bool  di  = old >= pv;
                    float vm  = di ? old : pv;
                    float nv  = vm + c[i];
                    if (xb + i > j) nv = NEGV;
                    v[i] = nv;
                    w |= (di ? (1u << i) : 0u);
                    pv = old;
                }
                w |= fbits;
                g_dbits[((size_t)b*TYn + j)*32 + lane] = w;

                int jn = j + D;
                if (jn < ylen) {
                    const float4* p = colbase + (size_t)jn * stride4;
                    cb[d][0]=p[0]; cb[d][1]=p[1]; cb[d][2]=p[2]; cb[d][3]=p[3];
                }
            }
        }
    }
}

// -------------------- K5: backtrack (warp-cooperative, 1 warp per batch) ----
__global__ void __launch_bounds__(32)
bwd_kernel(const int* __restrict__ xl, const int* __restrict__ yl)
{
    int b = blockIdx.x, lane = threadIdx.x;
    int xlen = xl[b], ylen = yl[b];

    for (int j = ylen + lane; j < TYn; j += 32) g_xy[b*TYn + j] = 0;

    int idx = xlen - 1;
    for (int jhi = ylen - 1; jhi >= 0; jhi -= 32) {
        int steps = min(32, jhi + 1);
        int j = jhi - lane;
        int w0 = idx >> 4;
        unsigned d0 = 0xFFFFu, d1 = 0xFFFFu, d2 = 0xFFFFu;
        if (lane < steps) {
            const unsigned* p = g_dbits + ((size_t)b*TYn + j)*32;
            d0 = p[w0];
            if (w0 >= 1) d1 = p[w0-1];
            if (w0 >= 2) d2 = p[w0-2];
        }
        int myidx = 0;
        for (int s = 0; s < steps; s++) {
            int wsel = w0 - (idx >> 4);              // uniform: 0,1,2
            unsigned sel  = (wsel == 0) ? d0 : ((wsel == 1) ? d1 : d2);
            unsigned word = __shfl_sync(0xFFFFFFFFu, sel, s);
            if (lane == s) myidx = idx;
            idx += (int)((word >> (idx & 15)) & 1u) - 1;
        }
        if (lane < steps) g_xy[b*TYn + jhi - lane] = myidx;
    }
}

// -------------------- K6: duration histogram --------------------------------
__global__ void count_kernel(const int* __restrict__ yl)
{
    int i = blockIdx.x * blockDim.x + threadIdx.x;
    if (i >= Bn*TYn) return;
    int b = i / TYn, y = i % TYn;
    if (y < yl[b]) atomicAdd(&g_cnt[b*TXn + g_xy[i]], 1);
}

// -------------------- K7: y_mean / y_log_scale gathers -----------------------
__global__ void gather_kernel(const float* __restrict__ om,
                              const float* __restrict__ ols,
                              const int* __restrict__ yl,
                              float* __restrict__ out)
{
    int i = blockIdx.x * blockDim.x + threadIdx.x;
    if (i >= Bn*Cc*TYn) return;
    int b = i / (Cc*TYn);
    int r = i % (Cc*TYn);
    int c = r / TYn;
    int y = r % TYn;
    float m = 0.f, s = 0.f;
    if (y < yl[b]) {
        int x = g_xy[b*TYn + y];
        m = om [(size_t)(b*Cc + c)*TXn + x];
        s = ols[(size_t)(b*Cc + c)*TXn + x];
    }
    out[YMEAN_OFF + i] = m;
    out[YLOG_OFF  + i] = s;
}

// -------------------- K8: attn_out (zero + one-hot scatter) ------------------
__global__ void attn_kernel(const int* __restrict__ yl, float* __restrict__ out)
{
    int y = blockIdx.x, b = blockIdx.y, t = threadIdx.x;   // 128 threads, 4 x each
    int xi = (y < yl[b]) ? g_xy[b*TYn + y] : -1;
    int x4 = t << 2;
    float4 r = make_float4(0.f, 0.f, 0.f, 0.f);
    if (xi >= x4 && xi < x4 + 4) ((float*)&r)[xi - x4] = 1.0f;
    *(float4*)&out[ATTN_OFF + ((size_t)b*TYn + y)*TXn + x4] = r;
}

// -------------------- K9: o_attn_dur -----------------------------------------
__global__ void dur_kernel(const int* __restrict__ xl, float* __restrict__ out)
{
    int i = blockIdx.x * blockDim.x + threadIdx.x;
    if (i >= Bn*TXn) return;
    int b = i / TXn, x = i % TXn;
    out[OADUR_OFF + i] = (x < xl[b]) ? log1pf((float)g_cnt[i]) : 0.f;
}

// -------------------- launch ---------------------------------------------------
extern "C" void kernel_launch(void* const* d_in, const int* in_sizes, int n_in,
                              void* d_out, int out_size)
{
    const float* om   = (const float*)d_in[0];   // o_mean      [B,C,TX]
    const float* ols  = (const float*)d_in[1];   // o_log_scale [B,C,TX]
    const float* odur = (const float*)d_in[2];   // o_dur_log   [B,1,TX]
    const float* z    = (const float*)d_in[3];   // z           [B,C,TY]
    const int*   xlen = (const int*)  d_in[4];   // x_lengths   [B]
    const int*   ylen = (const int*)  d_in[5];   // y_lengths   [B]
    float* out = (float*)d_out;

    prepx_kernel<<<(Bn*TXn + 255)/256, 256>>>(om, ols, odur, out);
    prepz_kernel<<<(Bn*Cc*TYn + 255)/256, 256>>>(z, ylen, out);
    gemm_kernel<<<dim3(TXn/64, TYn/64, Bn), 256>>>(xlen, ylen);
    fwd_kernel<<<Bn, 32>>>(xlen, ylen);
    bwd_kernel<<<Bn, 32>>>(xlen, ylen);
    count_kernel<<<(Bn*TYn + 255)/256, 256>>>(ylen);
    gather_kernel<<<(Bn*Cc*TYn + 255)/256, 256>>>(om, ols, ylen, out);
    attn_kernel<<<dim3(TYn, Bn), 128>>>(ylen, out);
    dur_kernel<<<(Bn*TXn + 255)/256, 256>>>(xlen, out);
}